// round 6
// baseline (speedup 1.0000x reference)
#include <cuda_runtime.h>
#include <cstdint>

#define LQ 2048
#define DIM 128
#define NB 8
#define KSPLIT 4
#define ROWS (NB*LQ)
#define NELE ((size_t)ROWS * DIM)

// deterministic scratch (no allocations allowed)
__device__ float g_rowsum_part[16][ROWS];        // 1 MB
__device__ float g_inv[ROWS];                    // 64 KB
__device__ float g_qt[NELE];                     // 8 MB: tf32(q / sqrt(128))
__device__ float g_vt[NELE];                     // 8 MB: tf32(v)
__device__ float g_w[NELE];                      // 8 MB: tf32(inv[i]*v[i,d])
__device__ float g_pout[KSPLIT][NELE];           // 32 MB

// ---------- helpers ----------
static __device__ __forceinline__ float tf32r(float x) {
    uint32_t u;
    asm("cvt.rna.tf32.f32 %0, %1;" : "=r"(u) : "f"(x));
    return __uint_as_float(u);
}

static __device__ __forceinline__ void mma8(float c[4], const float a[4], const float b[2]) {
    asm volatile(
        "mma.sync.aligned.m16n8k8.row.col.f32.tf32.tf32.f32 "
        "{%0,%1,%2,%3}, {%4,%5,%6,%7}, {%8,%9}, {%0,%1,%2,%3};\n"
        : "+f"(c[0]), "+f"(c[1]), "+f"(c[2]), "+f"(c[3])
        : "r"(__float_as_uint(a[0])), "r"(__float_as_uint(a[1])),
          "r"(__float_as_uint(a[2])), "r"(__float_as_uint(a[3])),
          "r"(__float_as_uint(b[0])), "r"(__float_as_uint(b[1])));
}

static __device__ __forceinline__ void cp16(void* dst, const void* src) {
    unsigned sd = (unsigned)__cvta_generic_to_shared(dst);
    asm volatile("cp.async.ca.shared.global [%0], [%1], 16;" :: "r"(sd), "l"(src));
}
static __device__ __forceinline__ void cp4(void* dst, const void* src) {
    unsigned sd = (unsigned)__cvta_generic_to_shared(dst);
    asm volatile("cp.async.ca.shared.global [%0], [%1], 4;" :: "r"(sd), "l"(src));
}
#define CPC  asm volatile("cp.async.commit_group;")
#define CPW2 asm volatile("cp.async.wait_group 2;")

// ===== Kernel 0: pre-round operands to tf32 (scale folded into q) =====
__global__ void k_prep_qv(const float* __restrict__ q, const float* __restrict__ v)
{
    const float sc = 0.08838834764831845f;  // 1/sqrt(128)
    const size_t i = ((size_t)blockIdx.x * 256 + threadIdx.x) * 4;
    if (i < NELE) {
        float4 t = *(const float4*)(q + i);
        t.x = tf32r(t.x * sc); t.y = tf32r(t.y * sc);
        t.z = tf32r(t.z * sc); t.w = tf32r(t.w * sc);
        *(float4*)&g_qt[i] = t;
    } else {
        const size_t j = i - NELE;
        float4 t = *(const float4*)(v + j);
        t.x = tf32r(t.x); t.y = tf32r(t.y);
        t.z = tf32r(t.z); t.w = tf32r(t.w);
        *(float4*)&g_vt[j] = t;
    }
}

// ===== Kernel 1: p = tf32(exp(q' @ v'^T)) + rowsum partials =====
// 4-stage cp.async pipeline, BK=8. Static smem: 2 * 4*128*12*4 = 49152 B (=48KB)
__global__ __launch_bounds__(256, 2) void k_scores_exp(float* __restrict__ attn)
{
    __shared__ float Qs[4][128][12];
    __shared__ float Vs[4][128][12];

    const int b  = blockIdx.z;
    const int jb = blockIdx.x;
    const int i0 = blockIdx.y * 128;
    const int j0 = jb * 128;

    const int tid  = threadIdx.x;
    const int lane = tid & 31;
    const int warp = tid >> 5;
    const int wm = (warp >> 2) * 64;
    const int wn = (warp & 3) * 32;
    const int g  = lane >> 2;
    const int kc = lane & 3;

    const float* qb = g_qt + ((size_t)b * LQ + i0) * DIM;
    const float* vb = g_vt + ((size_t)b * LQ + j0) * DIM;

    const int row2 = tid >> 1;          // 0..127
    const int ch   = (tid & 1) * 4;     // 0 or 4

    float acc[4][4][4];
    #pragma unroll
    for (int mt = 0; mt < 4; mt++)
        #pragma unroll
        for (int nt = 0; nt < 4; nt++)
            #pragma unroll
            for (int e = 0; e < 4; e++) acc[mt][nt][e] = 0.0f;

    // prologue: stages 0..2 (one group each)
    #pragma unroll
    for (int p = 0; p < 3; p++) {
        const int k0 = p * 8;
        cp16(&Qs[p][row2][ch], qb + (size_t)row2 * DIM + k0 + ch);
        cp16(&Vs[p][row2][ch], vb + (size_t)row2 * DIM + k0 + ch);
        CPC;
    }

    const int NIT = DIM / 8;   // 16
    #pragma unroll
    for (int kt = 0; kt < NIT; kt++) {
        const int st = kt & 3;
        CPW2;                   // stage kt resident
        __syncthreads();        // all warps done with the buffer we're about to refill
        if (kt + 3 < NIT) {
            const int sn = (kt + 3) & 3;
            const int k0 = (kt + 3) * 8;
            cp16(&Qs[sn][row2][ch], qb + (size_t)row2 * DIM + k0 + ch);
            cp16(&Vs[sn][row2][ch], vb + (size_t)row2 * DIM + k0 + ch);
        }
        CPC;                    // empty group in tail keeps accounting uniform

        float af[4][4], bf[4][2];
        #pragma unroll
        for (int mt = 0; mt < 4; mt++) {
            const int r = wm + mt * 16 + g;
            af[mt][0] = Qs[st][r][kc];
            af[mt][1] = Qs[st][r + 8][kc];
            af[mt][2] = Qs[st][r][kc + 4];
            af[mt][3] = Qs[st][r + 8][kc + 4];
        }
        #pragma unroll
        for (int nt = 0; nt < 4; nt++) {
            const int n = wn + nt * 8 + g;
            bf[nt][0] = Vs[st][n][kc];
            bf[nt][1] = Vs[st][n][kc + 4];
        }
        #pragma unroll
        for (int mt = 0; mt < 4; mt++)
            #pragma unroll
            for (int nt = 0; nt < 4; nt++)
                mma8(acc[mt][nt], af[mt], bf[nt]);
    }

    __syncthreads();            // everyone done reading tiles; reuse smem as rs
    float* rs = &Qs[0][0][0];   // 512 floats

    // epilogue: exp (scale folded), tf32-round, store, rowsum partials
    float* op = attn + ((size_t)b * LQ + i0) * LQ + j0;
    #pragma unroll
    for (int mt = 0; mt < 4; mt++) {
        const int r0 = wm + mt * 16 + g;
        float s0 = 0.0f, s1 = 0.0f;
        #pragma unroll
        for (int nt = 0; nt < 4; nt++) {
            const int c0 = wn + nt * 8 + kc * 2;
            float p0 = tf32r(__expf(acc[mt][nt][0]));
            float p1 = tf32r(__expf(acc[mt][nt][1]));
            float p2 = tf32r(__expf(acc[mt][nt][2]));
            float p3 = tf32r(__expf(acc[mt][nt][3]));
            *(float2*)(op + (size_t)r0 * LQ + c0)       = make_float2(p0, p1);
            *(float2*)(op + (size_t)(r0 + 8) * LQ + c0) = make_float2(p2, p3);
            s0 += p0 + p1;
            s1 += p2 + p3;
        }
        s0 += __shfl_xor_sync(0xFFFFFFFFu, s0, 1);
        s0 += __shfl_xor_sync(0xFFFFFFFFu, s0, 2);
        s1 += __shfl_xor_sync(0xFFFFFFFFu, s1, 1);
        s1 += __shfl_xor_sync(0xFFFFFFFFu, s1, 2);
        if (kc == 0) { rs[r0 * 4 + (warp & 3)] = s0; rs[(r0 + 8) * 4 + (warp & 3)] = s1; }
    }
    __syncthreads();
    if (tid < 128) {
        float t = rs[tid * 4] + rs[tid * 4 + 1] + rs[tid * 4 + 2] + rs[tid * 4 + 3];
        g_rowsum_part[jb][(size_t)b * LQ + i0 + tid] = t;
    }
}

// ===== Kernel 2: inv per row (fixed order) =====
__global__ void k_rowsum()
{
    const int row = blockIdx.x * 256 + threadIdx.x;
    float s = 0.0f;
    #pragma unroll
    for (int jb = 0; jb < 16; jb++) s += g_rowsum_part[jb][row];
    g_inv[row] = 1.0f / s;
}

// ===== Kernel 2b: w = tf32(inv[i] * v[i,d]) =====
__global__ void k_prep_w(const float* __restrict__ v)
{
    const size_t i = ((size_t)blockIdx.x * 256 + threadIdx.x) * 4;
    const float inv = g_inv[i / DIM];
    float4 vv = *(const float4*)(v + i);
    vv.x = tf32r(vv.x * inv); vv.y = tf32r(vv.y * inv);
    vv.z = tf32r(vv.z * inv); vv.w = tf32r(vv.w * inv);
    *(float4*)&g_w[i] = vv;
}

// ===== Kernel 3: normalize attn in place + partial out = p^T @ w =====
// 4-stage cp.async pipeline, BK=8. Static smem: 2 * 4*8*136*4 + 4*8*4 = 34,944 B
__global__ __launch_bounds__(256, 2) void k_av_norm(float* __restrict__ attn)
{
    __shared__ float As[4][8][136];
    __shared__ float Bs[4][8][136];
    __shared__ float Is[4][8];

    const int jb = blockIdx.x;
    const int b  = blockIdx.y;
    const int ks = blockIdx.z;
    const int j0 = jb * 128;
    const int ibase = ks * (LQ / KSPLIT);

    const int tid  = threadIdx.x;
    const int lane = tid & 31;
    const int warp = tid >> 5;
    const int wm = (warp >> 2) * 64;
    const int wn = (warp & 3) * 32;
    const int g  = lane >> 2;
    const int kc = lane & 3;

    float* ab = attn + (size_t)b * LQ * LQ + j0;       // (i, j0+m) at ab[i*LQ + m]
    const float* wb = g_w + (size_t)b * LQ * DIM;      // inv-folded, tf32-rounded v
    const float* iv = g_inv + (size_t)b * LQ;

    const int kr  = warp;        // 0..7 (one k-row per warp)
    const int lc4 = lane * 4;    // 0..124

    float acc[4][4][4];
    #pragma unroll
    for (int mt = 0; mt < 4; mt++)
        #pragma unroll
        for (int nt = 0; nt < 4; nt++)
            #pragma unroll
            for (int e = 0; e < 4; e++) acc[mt][nt][e] = 0.0f;

    // prologue: stages 0..2
    #pragma unroll
    for (int p = 0; p < 3; p++) {
        const int i0 = ibase + p * 8;
        cp16(&As[p][kr][lc4], ab + (size_t)(i0 + kr) * LQ + lc4);
        cp16(&Bs[p][kr][lc4], wb + (size_t)(i0 + kr) * DIM + lc4);
        if (tid < 8) cp4(&Is[p][tid], iv + i0 + tid);
        CPC;
    }

    const int NIT = (LQ / KSPLIT) / 8;   // 64
    #pragma unroll 4
    for (int kt = 0; kt < NIT; kt++) {
        const int st = kt & 3;
        CPW2;
        __syncthreads();
        if (kt + 3 < NIT) {
            const int sn = (kt + 3) & 3;
            const int i0n = ibase + (kt + 3) * 8;
            cp16(&As[sn][kr][lc4], ab + (size_t)(i0n + kr) * LQ + lc4);
            cp16(&Bs[sn][kr][lc4], wb + (size_t)(i0n + kr) * DIM + lc4);
            if (tid < 8) cp4(&Is[sn][tid], iv + i0n + tid);
        }
        CPC;

        // write back normalized attn (each element exactly once across grid)
        {
            const int i0 = ibase + kt * 8;
            const float iv0 = Is[st][kr];
            float4 a0 = *(const float4*)&As[st][kr][lc4];
            a0.x *= iv0; a0.y *= iv0; a0.z *= iv0; a0.w *= iv0;
            *(float4*)(ab + (size_t)(i0 + kr) * LQ + lc4) = a0;
        }

        float af[4][4], bf[4][2];
        #pragma unroll
        for (int mt = 0; mt < 4; mt++) {
            const int m = wm + mt * 16 + g;
            af[mt][0] = As[st][kc][m];
            af[mt][1] = As[st][kc][m + 8];
            af[mt][2] = As[st][kc + 4][m];
            af[mt][3] = As[st][kc + 4][m + 8];
        }
        #pragma unroll
        for (int nt = 0; nt < 4; nt++) {
            const int n = wn + nt * 8 + g;
            bf[nt][0] = Bs[st][kc][n];
            bf[nt][1] = Bs[st][kc + 4][n];
        }
        #pragma unroll
        for (int mt = 0; mt < 4; mt++)
            #pragma unroll
            for (int nt = 0; nt < 4; nt++)
                mma8(acc[mt][nt], af[mt], bf[nt]);
    }

    // epilogue -> split-K partial buffer
    float* op = g_pout[ks] + ((size_t)b * LQ + j0) * DIM;
    #pragma unroll
    for (int mt = 0; mt < 4; mt++) {
        const int r0 = wm + mt * 16 + g;
        #pragma unroll
        for (int nt = 0; nt < 4; nt++) {
            const int c0 = wn + nt * 8 + kc * 2;
            *(float2*)(op + (size_t)r0 * DIM + c0)       = make_float2(acc[mt][nt][0], acc[mt][nt][1]);
            *(float2*)(op + (size_t)(r0 + 8) * DIM + c0) = make_float2(acc[mt][nt][2], acc[mt][nt][3]);
        }
    }
}

// ===== Kernel 4: out = sum over split-K partials (fixed order) =====
__global__ void k_out_reduce(float* __restrict__ out)
{
    const size_t i = ((size_t)blockIdx.x * 256 + threadIdx.x) * 4;
    float4 a = *(const float4*)&g_pout[0][i];
    float4 b = *(const float4*)&g_pout[1][i];
    float4 c = *(const float4*)&g_pout[2][i];
    float4 d = *(const float4*)&g_pout[3][i];
    a.x = a.x + b.x + c.x + d.x;
    a.y = a.y + b.y + c.y + d.y;
    a.z = a.z + b.z + c.z + d.z;
    a.w = a.w + b.w + c.w + d.w;
    *(float4*)(out + i) = a;
}

// ===== launch =====
extern "C" void kernel_launch(void* const* d_in, const int* in_sizes, int n_in,
                              void* d_out, int out_size)
{
    const float* q = (const float*)d_in[0];
    // d_in[1] = k : unused by the reference computation
    const float* v = (const float*)d_in[2];

    float* out  = (float*)d_out;                 // [8, 2048, 128]
    float* attn = out + (size_t)NB * LQ * DIM;   // [8, 2048, 2048]

    k_prep_qv<<<2 * NELE / 1024, 256>>>(q, v);
    k_scores_exp<<<dim3(16, 16, NB), 256>>>(attn);
    k_rowsum<<<ROWS / 256, 256>>>();
    k_prep_w<<<NELE / 1024, 256>>>(v);
    k_av_norm<<<dim3(16, NB, KSPLIT), 256>>>(attn);
    k_out_reduce<<<NELE / 1024, 256>>>(out);
}

// round 8
// speedup vs baseline: 1.1672x; 1.1672x over previous
#include <cuda_runtime.h>
#include <cstdint>

#define LQ 2048
#define DIM 128
#define NB 8
#define KSPLIT 2
#define ROWS (NB*LQ)
#define NELE ((size_t)ROWS * DIM)

// deterministic scratch (no allocations allowed)
__device__ float g_rowsum_part[16][ROWS];        // 1 MB
__device__ float g_inv[ROWS];                    // 64 KB
__device__ float g_qt[NELE];                     // 8 MB: tf32(q / sqrt(128))
__device__ float g_vt[NELE];                     // 8 MB: tf32(v)
__device__ float g_w[NELE];                      // 8 MB: tf32(inv[i]*v[i,d])
__device__ float g_pout[KSPLIT][NELE];           // 16 MB

// ---------- helpers ----------
static __device__ __forceinline__ float tf32r(float x) {
    uint32_t u;
    asm("cvt.rna.tf32.f32 %0, %1;" : "=r"(u) : "f"(x));
    return __uint_as_float(u);
}

static __device__ __forceinline__ void mma8(float c[4], const float a[4], const float b[2]) {
    asm volatile(
        "mma.sync.aligned.m16n8k8.row.col.f32.tf32.tf32.f32 "
        "{%0,%1,%2,%3}, {%4,%5,%6,%7}, {%8,%9}, {%0,%1,%2,%3};\n"
        : "+f"(c[0]), "+f"(c[1]), "+f"(c[2]), "+f"(c[3])
        : "r"(__float_as_uint(a[0])), "r"(__float_as_uint(a[1])),
          "r"(__float_as_uint(a[2])), "r"(__float_as_uint(a[3])),
          "r"(__float_as_uint(b[0])), "r"(__float_as_uint(b[1])));
}

static __device__ __forceinline__ void cp16(void* dst, const void* src) {
    unsigned sd = (unsigned)__cvta_generic_to_shared(dst);
    asm volatile("cp.async.ca.shared.global [%0], [%1], 16;" :: "r"(sd), "l"(src));
}
static __device__ __forceinline__ void cp4(void* dst, const void* src) {
    unsigned sd = (unsigned)__cvta_generic_to_shared(dst);
    asm volatile("cp.async.ca.shared.global [%0], [%1], 4;" :: "r"(sd), "l"(src));
}
#define CPC  asm volatile("cp.async.commit_group;")
#define CPW1 asm volatile("cp.async.wait_group 1;")
#define CPW0 asm volatile("cp.async.wait_group 0;")

// ===== Kernel 0: pre-round operands to tf32 (scale folded into q) =====
__global__ void k_prep_qv(const float* __restrict__ q, const float* __restrict__ v)
{
    const float sc = 0.08838834764831845f;  // 1/sqrt(128)
    const size_t i = ((size_t)blockIdx.x * 256 + threadIdx.x) * 4;
    if (i < NELE) {
        float4 t = *(const float4*)(q + i);
        t.x = tf32r(t.x * sc); t.y = tf32r(t.y * sc);
        t.z = tf32r(t.z * sc); t.w = tf32r(t.w * sc);
        *(float4*)&g_qt[i] = t;
    } else {
        const size_t j = i - NELE;
        float4 t = *(const float4*)(v + j);
        t.x = tf32r(t.x); t.y = tf32r(t.y);
        t.z = tf32r(t.z); t.w = tf32r(t.w);
        *(float4*)&g_vt[j] = t;
    }
}

// ===== Kernel 1: p = tf32(exp(q' @ v'^T)) + rowsum partials =====
// 4 warps, 64x64 warp tiles (2x2): halves A-fragment smem re-reads.
// static smem: Qs[2][128][20] + Vs[2][128][20] + rs[128][2] = 41,984 B
__global__ __launch_bounds__(128, 2) void k_scores_exp(float* __restrict__ attn)
{
    __shared__ float Qs[2][128][20];
    __shared__ float Vs[2][128][20];
    __shared__ float rs[128][2];

    const int b  = blockIdx.z;
    const int jb = blockIdx.x;
    const int i0 = blockIdx.y * 128;
    const int j0 = jb * 128;

    const int tid  = threadIdx.x;
    const int lane = tid & 31;
    const int warp = tid >> 5;          // 0..3
    const int wm = (warp >> 1) * 64;
    const int wn = (warp & 1) * 64;
    const int g   = lane >> 2;
    const int kc4 = lane & 3;

    const float* qb = g_qt + ((size_t)b * LQ + i0) * DIM;
    const float* vb = g_vt + ((size_t)b * LQ + j0) * DIM;

    const int lr  = tid >> 2;           // 0..31
    const int lcc = (tid & 3) * 4;      // 0,4,8,12

    float acc[4][8][4];
    #pragma unroll
    for (int mt = 0; mt < 4; mt++)
        #pragma unroll
        for (int nt = 0; nt < 8; nt++)
            #pragma unroll
            for (int e = 0; e < 4; e++) acc[mt][nt][e] = 0.0f;

    // prologue: stage 0 (4 row-blocks of 32)
    #pragma unroll
    for (int h = 0; h < 4; h++) {
        cp16(&Qs[0][lr + h * 32][lcc], qb + (size_t)(lr + h * 32) * DIM + lcc);
        cp16(&Vs[0][lr + h * 32][lcc], vb + (size_t)(lr + h * 32) * DIM + lcc);
    }
    CPC;

    #pragma unroll
    for (int kt = 0; kt < 8; kt++) {
        const int st = kt & 1;
        if (kt < 7) {
            const int k0 = (kt + 1) * 16;
            const int sn = st ^ 1;
            #pragma unroll
            for (int h = 0; h < 4; h++) {
                cp16(&Qs[sn][lr + h * 32][lcc], qb + (size_t)(lr + h * 32) * DIM + k0 + lcc);
                cp16(&Vs[sn][lr + h * 32][lcc], vb + (size_t)(lr + h * 32) * DIM + k0 + lcc);
            }
            CPC; CPW1;
        } else {
            CPW0;
        }
        __syncthreads();

        #pragma unroll
        for (int kk = 0; kk < 16; kk += 8) {
            const int kc = kk + kc4;
            float af[4][4], bf[8][2];
            #pragma unroll
            for (int mt = 0; mt < 4; mt++) {
                const int r = wm + mt * 16 + g;
                af[mt][0] = Qs[st][r][kc];
                af[mt][1] = Qs[st][r + 8][kc];
                af[mt][2] = Qs[st][r][kc + 4];
                af[mt][3] = Qs[st][r + 8][kc + 4];
            }
            #pragma unroll
            for (int nt = 0; nt < 8; nt++) {
                const int n = wn + nt * 8 + g;
                bf[nt][0] = Vs[st][n][kc];
                bf[nt][1] = Vs[st][n][kc + 4];
            }
            #pragma unroll
            for (int mt = 0; mt < 4; mt++)
                #pragma unroll
                for (int nt = 0; nt < 8; nt++)
                    mma8(acc[mt][nt], af[mt], bf[nt]);
        }
        __syncthreads();
    }

    // epilogue: exp (scale folded), tf32-round, store, rowsum partials
    float* op = attn + ((size_t)b * LQ + i0) * LQ + j0;
    #pragma unroll
    for (int mt = 0; mt < 4; mt++) {
        const int r0 = wm + mt * 16 + g;
        float s0 = 0.0f, s1 = 0.0f;
        #pragma unroll
        for (int nt = 0; nt < 8; nt++) {
            const int c0 = wn + nt * 8 + kc4 * 2;
            float p0 = tf32r(__expf(acc[mt][nt][0]));
            float p1 = tf32r(__expf(acc[mt][nt][1]));
            float p2 = tf32r(__expf(acc[mt][nt][2]));
            float p3 = tf32r(__expf(acc[mt][nt][3]));
            *(float2*)(op + (size_t)r0 * LQ + c0)       = make_float2(p0, p1);
            *(float2*)(op + (size_t)(r0 + 8) * LQ + c0) = make_float2(p2, p3);
            s0 += p0 + p1;
            s1 += p2 + p3;
        }
        s0 += __shfl_xor_sync(0xFFFFFFFFu, s0, 1);
        s0 += __shfl_xor_sync(0xFFFFFFFFu, s0, 2);
        s1 += __shfl_xor_sync(0xFFFFFFFFu, s1, 1);
        s1 += __shfl_xor_sync(0xFFFFFFFFu, s1, 2);
        if (kc4 == 0) { rs[r0][warp & 1] = s0; rs[r0 + 8][warp & 1] = s1; }
    }
    __syncthreads();
    // 128 threads = 128 rows
    {
        float t = rs[tid][0] + rs[tid][1];
        g_rowsum_part[jb][(size_t)b * LQ + i0 + tid] = t;
    }
}

// ===== Kernel 2: inv per row (fixed order) =====
__global__ void k_rowsum()
{
    const int row = blockIdx.x * 256 + threadIdx.x;
    float s = 0.0f;
    #pragma unroll
    for (int jb = 0; jb < 16; jb++) s += g_rowsum_part[jb][row];
    g_inv[row] = 1.0f / s;
}

// ===== Kernel 2b: w = tf32(inv[i] * v[i,d]) =====
__global__ void k_prep_w(const float* __restrict__ v)
{
    const size_t i = ((size_t)blockIdx.x * 256 + threadIdx.x) * 4;
    const float inv = g_inv[i / DIM];
    float4 vv = *(const float4*)(v + i);
    vv.x = tf32r(vv.x * inv); vv.y = tf32r(vv.y * inv);
    vv.z = tf32r(vv.z * inv); vv.w = tf32r(vv.w * inv);
    *(float4*)&g_w[i] = vv;
}

// ===== Kernel 3: normalize attn in place + partial out = p^T @ w =====
// (proven R5 structure; split-K now 2)
__global__ __launch_bounds__(256, 2) void k_av_norm(float* __restrict__ attn)
{
    const int jb = blockIdx.x;
    const int b  = blockIdx.y;
    const int ks = blockIdx.z;
    const int j0 = jb * 128;
    const int ibase = ks * (LQ / KSPLIT);

    __shared__ float As[2][16][136];
    __shared__ float Bs[2][16][136];
    __shared__ float Is[2][16];

    const int tid  = threadIdx.x;
    const int lane = tid & 31;
    const int warp = tid >> 5;
    const int wm = (warp >> 2) * 64;
    const int wn = (warp & 3) * 32;
    const int g  = lane >> 2;

    float* ab = attn + (size_t)b * LQ * LQ + j0;
    const float* wb = g_w + (size_t)b * LQ * DIM;
    const float* iv = g_inv + (size_t)b * LQ;

    const int kr  = warp;
    const int lc4 = lane * 4;

    float acc[4][4][4];
    #pragma unroll
    for (int mt = 0; mt < 4; mt++)
        #pragma unroll
        for (int nt = 0; nt < 4; nt++)
            #pragma unroll
            for (int e = 0; e < 4; e++) acc[mt][nt][e] = 0.0f;

    {
        const int i0 = ibase;
        cp16(&As[0][kr][lc4],     ab + (size_t)(i0 + kr) * LQ + lc4);
        cp16(&As[0][kr + 8][lc4], ab + (size_t)(i0 + kr + 8) * LQ + lc4);
        cp16(&Bs[0][kr][lc4],     wb + (size_t)(i0 + kr) * DIM + lc4);
        cp16(&Bs[0][kr + 8][lc4], wb + (size_t)(i0 + kr + 8) * DIM + lc4);
        if (tid < 16) cp4(&Is[0][tid], iv + i0 + tid);
        CPC;
    }

    const int NIT = (LQ / KSPLIT) / 16;   // 64
    #pragma unroll 2
    for (int kt = 0; kt < NIT; kt++) {
        const int st = kt & 1;
        if (kt < NIT - 1) {
            const int i0n = ibase + (kt + 1) * 16;
            const int sn = st ^ 1;
            cp16(&As[sn][kr][lc4],     ab + (size_t)(i0n + kr) * LQ + lc4);
            cp16(&As[sn][kr + 8][lc4], ab + (size_t)(i0n + kr + 8) * LQ + lc4);
            cp16(&Bs[sn][kr][lc4],     wb + (size_t)(i0n + kr) * DIM + lc4);
            cp16(&Bs[sn][kr + 8][lc4], wb + (size_t)(i0n + kr + 8) * DIM + lc4);
            if (tid < 16) cp4(&Is[sn][tid], iv + i0n + tid);
            CPC; CPW1;
        } else {
            CPW0;
        }
        __syncthreads();

        // write back normalized attn (each element exactly once across grid)
        {
            const int i0 = ibase + kt * 16;
            const float iv0 = Is[st][kr], iv1 = Is[st][kr + 8];
            float4 a0 = *(const float4*)&As[st][kr][lc4];
            float4 a1 = *(const float4*)&As[st][kr + 8][lc4];
            a0.x *= iv0; a0.y *= iv0; a0.z *= iv0; a0.w *= iv0;
            a1.x *= iv1; a1.y *= iv1; a1.z *= iv1; a1.w *= iv1;
            *(float4*)(ab + (size_t)(i0 + kr) * LQ + lc4)     = a0;
            *(float4*)(ab + (size_t)(i0 + kr + 8) * LQ + lc4) = a1;
        }

        #pragma unroll
        for (int kk = 0; kk < 16; kk += 8) {
            const int kc = kk + (lane & 3);
            float af[4][4], bf[4][2];
            #pragma unroll
            for (int mt = 0; mt < 4; mt++) {
                const int m = wm + mt * 16 + g;
                af[mt][0] = As[st][kc][m];
                af[mt][1] = As[st][kc][m + 8];
                af[mt][2] = As[st][kc + 4][m];
                af[mt][3] = As[st][kc + 4][m + 8];
            }
            #pragma unroll
            for (int nt = 0; nt < 4; nt++) {
                const int n = wn + nt * 8 + g;
                bf[nt][0] = Bs[st][kc][n];
                bf[nt][1] = Bs[st][kc + 4][n];
            }
            #pragma unroll
            for (int mt = 0; mt < 4; mt++)
                #pragma unroll
                for (int nt = 0; nt < 4; nt++)
                    mma8(acc[mt][nt], af[mt], bf[nt]);
        }
        __syncthreads();
    }

    float* op = g_pout[ks] + ((size_t)b * LQ + j0) * DIM;
    #pragma unroll
    for (int mt = 0; mt < 4; mt++) {
        const int r0 = wm + mt * 16 + g;
        #pragma unroll
        for (int nt = 0; nt < 4; nt++) {
            const int c0 = wn + nt * 8 + (lane & 3) * 2;
            *(float2*)(op + (size_t)r0 * DIM + c0)       = make_float2(acc[mt][nt][0], acc[mt][nt][1]);
            *(float2*)(op + (size_t)(r0 + 8) * DIM + c0) = make_float2(acc[mt][nt][2], acc[mt][nt][3]);
        }
    }
}

// ===== Kernel 4: out = sum over split-K partials (fixed order) =====
__global__ void k_out_reduce(float* __restrict__ out)
{
    const size_t i = ((size_t)blockIdx.x * 256 + threadIdx.x) * 4;
    float4 a = *(const float4*)&g_pout[0][i];
    float4 b = *(const float4*)&g_pout[1][i];
    a.x = a.x + b.x;
    a.y = a.y + b.y;
    a.z = a.z + b.z;
    a.w = a.w + b.w;
    *(float4*)(out + i) = a;
}

// ===== launch =====
extern "C" void kernel_launch(void* const* d_in, const int* in_sizes, int n_in,
                              void* d_out, int out_size)
{
    const float* q = (const float*)d_in[0];
    // d_in[1] = k : unused by the reference computation
    const float* v = (const float*)d_in[2];

    float* out  = (float*)d_out;                 // [8, 2048, 128]
    float* attn = out + (size_t)NB * LQ * DIM;   // [8, 2048, 2048]

    k_prep_qv<<<2 * NELE / 1024, 256>>>(q, v);
    k_scores_exp<<<dim3(16, 16, NB), 128>>>(attn);
    k_rowsum<<<ROWS / 256, 256>>>();
    k_prep_w<<<NELE / 1024, 256>>>(v);
    k_av_norm<<<dim3(16, NB, KSPLIT), 256>>>(attn);
    k_out_reduce<<<NELE / 1024, 256>>>(out);
}